// round 5
// baseline (speedup 1.0000x reference)
#include <cuda_runtime.h>
#include <cuda_fp16.h>
#include <cstdint>

// DynamicFeedForward:
//   input_value [4,2048,512] f32
//   mask_tensor [4,2048,32] i32
//   weight      [50000,512] f32
//   bias        [50000]     f32
// out[b,s,m] = relu( dot(input[b,s,:], weight[mask[b,s,m],:]) + bias[mask[b,s,m]] )
//
// Phase 1: repack W -> fp16 table (halves gathered bytes; DRAM-floor bound).
// Phase 2: gather+dot, L2-bandwidth bound (~268MB from L2-resident fp16 table).

static constexpr int HIDDEN   = 512;
static constexpr int NCAND    = 32;
static constexpr int NROWS    = 50000;
static constexpr int THREADS  = 256;   // 8 warps = 8 tokens per CTA

__device__ __align__(16) __half g_wh[(size_t)NROWS * HIDDEN];   // 51.2 MB scratch

// ---------------- conversion: fp32 W -> fp16 table ----------------
// Default cache policy on W reads: lets surviving W lines stay in L2 across
// graph replays (the gather phase only keeps ~51MB hot out of 126MB L2).
__global__ __launch_bounds__(512)
void convert_kernel(const float* __restrict__ W, int n_vec8)
{
    int i = blockIdx.x * blockDim.x + threadIdx.x;   // one thread = 8 floats
    if (i >= n_vec8) return;
    const float4* w4 = reinterpret_cast<const float4*>(W) + (size_t)i * 2;
    float4 f0 = w4[0];
    float4 f1 = w4[1];
    __half2 h[4];
    h[0] = __floats2half2_rn(f0.x, f0.y);
    h[1] = __floats2half2_rn(f0.z, f0.w);
    h[2] = __floats2half2_rn(f1.x, f1.y);
    h[3] = __floats2half2_rn(f1.z, f1.w);
    reinterpret_cast<uint4*>(g_wh)[i] = *reinterpret_cast<uint4*>(h);   // write-back: table stays in L2
}

// ---------------- gather / dot ----------------
__device__ __forceinline__ float dot8(const uint4 v, const float4 aA, const float4 aB)
{
    const __half2* h = reinterpret_cast<const __half2*>(&v);
    float s = 0.f;
    float2 f;
    f = __half22float2(h[0]); s = fmaf(aA.x, f.x, s); s = fmaf(aA.y, f.y, s);
    f = __half22float2(h[1]); s = fmaf(aA.z, f.x, s); s = fmaf(aA.w, f.y, s);
    f = __half22float2(h[2]); s = fmaf(aB.x, f.x, s); s = fmaf(aB.y, f.y, s);
    f = __half22float2(h[3]); s = fmaf(aB.z, f.x, s); s = fmaf(aB.w, f.y, s);
    return s;
}

__global__ __launch_bounds__(THREADS, 6)
void dff_kernel(const float* __restrict__ inp,
                const int* __restrict__ mask,
                const float* __restrict__ B,
                float* __restrict__ out,
                int n_tokens)
{
    const int lane  = threadIdx.x & 31;
    const int token = blockIdx.x * 8 + (threadIdx.x >> 5);
    if (token >= n_tokens) return;

    // Stage this lane's 16 input floats: [8l,8l+8) and [256+8l,256+8l+8).
    const float* in_row = inp + (size_t)token * HIDDEN;
    const float4 a0 = *reinterpret_cast<const float4*>(in_row + 8 * lane + 0);
    const float4 a1 = *reinterpret_cast<const float4*>(in_row + 8 * lane + 4);
    const float4 a2 = *reinterpret_cast<const float4*>(in_row + 256 + 8 * lane + 0);
    const float4 a3 = *reinterpret_cast<const float4*>(in_row + 256 + 8 * lane + 4);

    // Lane l owns candidate l's index and bias.
    const int midx   = mask[(size_t)token * NCAND + lane];
    const float bval = __ldg(B + midx);

    float res = 0.f;

    #pragma unroll
    for (int c = 0; c < NCAND; c += 4) {
        const __half* w[4];
        #pragma unroll
        for (int k = 0; k < 4; k++) {
            const int idx = __shfl_sync(0xFFFFFFFFu, midx, c + k);
            w[k] = g_wh + (size_t)idx * HIDDEN;
        }

        float s[4];

        // Phase 1: first 512B span of each row (4 LDG.128 in flight).
        {
            uint4 v[4];
            #pragma unroll
            for (int k = 0; k < 4; k++)
                v[k] = __ldcg(reinterpret_cast<const uint4*>(w[k] + 8 * lane));
            #pragma unroll
            for (int k = 0; k < 4; k++)
                s[k] = dot8(v[k], a0, a1);
        }
        // Phase 2: second 512B span.
        {
            uint4 v[4];
            #pragma unroll
            for (int k = 0; k < 4; k++)
                v[k] = __ldcg(reinterpret_cast<const uint4*>(w[k] + 256 + 8 * lane));
            #pragma unroll
            for (int k = 0; k < 4; k++)
                s[k] += dot8(v[k], a2, a3);
        }

        #pragma unroll
        for (int off = 16; off > 0; off >>= 1) {
            #pragma unroll
            for (int k = 0; k < 4; k++)
                s[k] += __shfl_xor_sync(0xFFFFFFFFu, s[k], off);
        }

        #pragma unroll
        for (int k = 0; k < 4; k++)
            if (lane == c + k) res = s[k];
    }

    // Coalesced 128B store: lane l writes candidate l.
    out[(size_t)token * NCAND + lane] = fmaxf(res + bval, 0.0f);
}

extern "C" void kernel_launch(void* const* d_in, const int* in_sizes, int n_in,
                              void* d_out, int out_size)
{
    const float* inp  = (const float*)d_in[0];
    const int*   mask = (const int*)d_in[1];
    const float* W    = (const float*)d_in[2];
    const float* B    = (const float*)d_in[3];
    float* out = (float*)d_out;

    const int n_tokens = in_sizes[0] / HIDDEN;           // 8192
    const int n_vec8   = NROWS * HIDDEN / 8;             // 3.2M
    const int conv_blk = (n_vec8 + 511) / 512;

    convert_kernel<<<conv_blk, 512>>>(W, n_vec8);
    dff_kernel<<<(n_tokens + 7) / 8, THREADS>>>(inp, mask, B, out, n_tokens);
}

// round 6
// speedup vs baseline: 1.2808x; 1.2808x over previous
#include <cuda_runtime.h>
#include <cuda_fp16.h>
#include <cstdint>

// DynamicFeedForward:
//   input_value [4,2048,512] f32
//   mask_tensor [4,2048,32] i32
//   weight      [50000,512] f32
//   bias        [50000]     f32
// out[b,s,m] = relu( dot(input[b,s,:], weight[mask[b,s,m],:]) + bias[mask[b,s,m]] )
//
// Phase 1: repack W -> fp16 table (__ldcs on W: stream, don't evict the table).
// Phase 2: gather+dot, LTS-cap bound (~284MB from the L2-resident fp16 table),
//          software-pipelined one candidate-group ahead.

static constexpr int HIDDEN   = 512;
static constexpr int NCAND    = 32;
static constexpr int NROWS    = 50000;
static constexpr int THREADS  = 256;   // 8 warps = 8 tokens per CTA

__device__ __align__(16) __half g_wh[(size_t)NROWS * HIDDEN];   // 51.2 MB scratch

// ---------------- conversion: fp32 W -> fp16 table (R4-exact) ----------------
__global__ __launch_bounds__(256)
void convert_kernel(const float* __restrict__ W, int n_vec8)
{
    int i = blockIdx.x * blockDim.x + threadIdx.x;   // one thread = 8 floats
    if (i >= n_vec8) return;
    const float4* w4 = reinterpret_cast<const float4*>(W) + (size_t)i * 2;
    float4 f0 = __ldcs(w4 + 0);     // evict-first: don't let W evict the fp16 table
    float4 f1 = __ldcs(w4 + 1);
    __half2 h[4];
    h[0] = __floats2half2_rn(f0.x, f0.y);
    h[1] = __floats2half2_rn(f0.z, f0.w);
    h[2] = __floats2half2_rn(f1.x, f1.y);
    h[3] = __floats2half2_rn(f1.z, f1.w);
    reinterpret_cast<uint4*>(g_wh)[i] = *reinterpret_cast<uint4*>(h);   // write-back: table stays in L2
}

// ---------------- gather / dot ----------------
__device__ __forceinline__ float dot8(const uint4 v, const float4 aA, const float4 aB)
{
    const __half2* h = reinterpret_cast<const __half2*>(&v);
    float s = 0.f;
    float2 f;
    f = __half22float2(h[0]); s = fmaf(aA.x, f.x, s); s = fmaf(aA.y, f.y, s);
    f = __half22float2(h[1]); s = fmaf(aA.z, f.x, s); s = fmaf(aA.w, f.y, s);
    f = __half22float2(h[2]); s = fmaf(aB.x, f.x, s); s = fmaf(aB.y, f.y, s);
    f = __half22float2(h[3]); s = fmaf(aB.z, f.x, s); s = fmaf(aB.w, f.y, s);
    return s;
}

__global__ __launch_bounds__(THREADS)
void dff_kernel(const float* __restrict__ inp,
                const int* __restrict__ mask,
                const float* __restrict__ B,
                float* __restrict__ out,
                int n_tokens)
{
    const int lane  = threadIdx.x & 31;
    const int token = blockIdx.x * 8 + (threadIdx.x >> 5);
    if (token >= n_tokens) return;

    // Stage this lane's 16 input floats: [8l,8l+8) and [256+8l,256+8l+8).
    const float* in_row = inp + (size_t)token * HIDDEN;
    const float4 a0 = *reinterpret_cast<const float4*>(in_row + 8 * lane + 0);
    const float4 a1 = *reinterpret_cast<const float4*>(in_row + 8 * lane + 4);
    const float4 a2 = *reinterpret_cast<const float4*>(in_row + 256 + 8 * lane + 0);
    const float4 a3 = *reinterpret_cast<const float4*>(in_row + 256 + 8 * lane + 4);

    // Lane l owns candidate l's index and bias.
    const int midx   = mask[(size_t)token * NCAND + lane];
    const float bval = __ldg(B + midx);

    // Prologue: issue group 0's 8 loads.
    uint4 v0[4], v1[4];
    #pragma unroll
    for (int k = 0; k < 4; k++) {
        const int idx = __shfl_sync(0xFFFFFFFFu, midx, k);
        const __half* w = g_wh + (size_t)idx * HIDDEN;
        v0[k] = __ldcg(reinterpret_cast<const uint4*>(w + 8 * lane));
        v1[k] = __ldcg(reinterpret_cast<const uint4*>(w + 256 + 8 * lane));
    }

    float res = 0.f;

    #pragma unroll
    for (int c = 0; c < NCAND; c += 4) {
        // Consume current group's data.
        float s[4];
        #pragma unroll
        for (int k = 0; k < 4; k++)
            s[k] = dot8(v0[k], a0, a1) + dot8(v1[k], a2, a3);

        // Prefetch next group's 8 loads BEFORE the long shuffle-reduce chain.
        if (c + 4 < NCAND) {
            #pragma unroll
            for (int k = 0; k < 4; k++) {
                const int idx = __shfl_sync(0xFFFFFFFFu, midx, c + 4 + k);
                const __half* w = g_wh + (size_t)idx * HIDDEN;
                v0[k] = __ldcg(reinterpret_cast<const uint4*>(w + 8 * lane));
                v1[k] = __ldcg(reinterpret_cast<const uint4*>(w + 256 + 8 * lane));
            }
        }

        // Interleaved xor-reductions (loads fly underneath).
        #pragma unroll
        for (int off = 16; off > 0; off >>= 1) {
            #pragma unroll
            for (int k = 0; k < 4; k++)
                s[k] += __shfl_xor_sync(0xFFFFFFFFu, s[k], off);
        }

        #pragma unroll
        for (int k = 0; k < 4; k++)
            if (lane == c + k) res = s[k];
    }

    // Coalesced 128B store: lane l writes candidate l.
    out[(size_t)token * NCAND + lane] = fmaxf(res + bval, 0.0f);
}

extern "C" void kernel_launch(void* const* d_in, const int* in_sizes, int n_in,
                              void* d_out, int out_size)
{
    const float* inp  = (const float*)d_in[0];
    const int*   mask = (const int*)d_in[1];
    const float* W    = (const float*)d_in[2];
    const float* B    = (const float*)d_in[3];
    float* out = (float*)d_out;

    const int n_tokens = in_sizes[0] / HIDDEN;           // 8192
    const int n_vec8   = NROWS * HIDDEN / 8;             // 3.2M
    const int conv_blk = (n_vec8 + 255) / 256;

    convert_kernel<<<conv_blk, 256>>>(W, n_vec8);
    dff_kernel<<<(n_tokens + 7) / 8, THREADS>>>(inp, mask, B, out, n_tokens);
}